// round 8
// baseline (speedup 1.0000x reference)
#include <cuda_runtime.h>
#include <cuda_fp16.h>
#include <mma.h>

using namespace nvcuda;

#define N_NODES  100000
#define N_EDGES  1600000
#define N_GRAPHS 1000
#define D        64
#define NB_SCAN  ((N_NODES + 255) / 256)   // 391

// ---------------- device scratch (no allocations allowed) ----------------
__device__ int    g_deg[N_NODES];
__device__ int    g_off[N_NODES];           // CSR row offsets
__device__ int    g_cursor[N_NODES];        // fill cursors
__device__ int    g_bsum[NB_SCAN];
__device__ int    g_boff[NB_SCAN];
__device__ int    g_csr[N_EDGES];           // src indices grouped by dst
__device__ float  g_dinv[N_NODES];
__device__ __half g_hs[(size_t)N_NODES * D];    // fp16 prescaled messages
__device__ float  g_agg[(size_t)N_NODES * D];   // layer-1 aggregation output
__device__ float  g_pool[(size_t)N_GRAPHS * D]; // per-graph feature sums (RED target)

// ---------------- degree / norm (also zeroes pool sums) ----------------
__global__ void k_deg_init() {
    int i = blockIdx.x * blockDim.x + threadIdx.x;
    if (i < N_NODES) g_deg[i] = 1;  // self-loop
    if (i < N_GRAPHS * D) g_pool[i] = 0.f;
}

__global__ void k_deg_count(const int* __restrict__ ei) {
    int t = blockIdx.x * blockDim.x + threadIdx.x;
    if (t < N_EDGES / 4) {
        int4 d = ((const int4*)(ei + N_EDGES))[t];
        atomicAdd(&g_deg[d.x], 1);
        atomicAdd(&g_deg[d.y], 1);
        atomicAdd(&g_deg[d.z], 1);
        atomicAdd(&g_deg[d.w], 1);
    }
}

__global__ void k_dinv() {
    int i = blockIdx.x * blockDim.x + threadIdx.x;
    if (i < N_NODES) {
        g_dinv[i] = rsqrtf((float)g_deg[i]);
        g_cursor[i] = 0;
    }
}

// ---------------- 3-pass exclusive scan of (deg-1) into g_off ----------------
__global__ __launch_bounds__(256) void k_scanA() {
    __shared__ int s[256];
    int tid = threadIdx.x;
    int i = blockIdx.x * 256 + tid;
    int v = (i < N_NODES) ? (g_deg[i] - 1) : 0;
    s[tid] = v;
    __syncthreads();
#pragma unroll
    for (int o = 1; o < 256; o <<= 1) {
        int t = (tid >= o) ? s[tid - o] : 0;
        __syncthreads();
        s[tid] += t;
        __syncthreads();
    }
    if (i < N_NODES) g_off[i] = s[tid] - v;          // exclusive
    if (tid == 255) g_bsum[blockIdx.x] = s[255];
}

__global__ __launch_bounds__(512) void k_scanB() {
    __shared__ int s[512];
    int tid = threadIdx.x;
    int v = (tid < NB_SCAN) ? g_bsum[tid] : 0;
    s[tid] = v;
    __syncthreads();
#pragma unroll
    for (int o = 1; o < 512; o <<= 1) {
        int t = (tid >= o) ? s[tid - o] : 0;
        __syncthreads();
        s[tid] += t;
        __syncthreads();
    }
    if (tid < NB_SCAN) g_boff[tid] = s[tid] - v;     // exclusive
}

__global__ __launch_bounds__(256) void k_scanC() {
    int i = blockIdx.x * 256 + threadIdx.x;
    if (i < N_NODES) g_off[i] += g_boff[i >> 8];
}

// ---------------- CSR fill: group src indices by dst ----------------
__global__ __launch_bounds__(256) void k_fill(const int* __restrict__ ei) {
    int e = blockIdx.x * blockDim.x + threadIdx.x;
    if (e < N_EDGES) {
        int src = ei[e];
        int dst = ei[N_EDGES + e];
        int pos = g_off[dst] + atomicAdd(&g_cursor[dst], 1);
        g_csr[pos] = src;
    }
}

// ---------------- tensor-core GEMM: hs = fp16( (act(in)*dinv[row]) @ W ) ----------------
template<bool RELU_IN>
__global__ __launch_bounds__(256) void k_gcn_gemm(const float* __restrict__ in,
                                                  const float* __restrict__ W,
                                                  __half* __restrict__ hs) {
    __shared__ __align__(16) char smem_raw[128 * 68 * 4];
    __half (*Xh)[72] = (__half(*)[72])smem_raw;              // 128x72 fp16
    __half (*Wh)[72] = (__half(*)[72])(smem_raw + 18432);    // 64x72  fp16
    float  (*Out)[68] = (float(*)[68])smem_raw;              // 128x68 fp32 (after sync)

    const int tid = threadIdx.x;
    const int rowBase = blockIdx.x * 128;

#pragma unroll
    for (int i = 0; i < 4; i++) {
        int f4 = tid + i * 256;
        int r  = f4 >> 4;
        int c4 = f4 & 15;
        float4 v = ((const float4*)W)[f4];
        __half2 h0 = __floats2half2_rn(v.x, v.y);
        __half2 h1 = __floats2half2_rn(v.z, v.w);
        __half2* p = (__half2*)&Wh[r][c4 * 4];
        p[0] = h0; p[1] = h1;
    }

#pragma unroll
    for (int i = 0; i < 8; i++) {
        int f4  = tid + i * 256;
        int r   = f4 >> 4;
        int c4  = f4 & 15;
        int row = rowBase + r;
        float4 v = make_float4(0.f, 0.f, 0.f, 0.f);
        float di = 0.f;
        if (row < N_NODES) {
            v = ((const float4*)in)[(size_t)row * 16 + c4];
            di = g_dinv[row];
        }
        if (RELU_IN) {
            v.x = fmaxf(v.x, 0.f); v.y = fmaxf(v.y, 0.f);
            v.z = fmaxf(v.z, 0.f); v.w = fmaxf(v.w, 0.f);
        }
        __half2 h0 = __floats2half2_rn(v.x * di, v.y * di);
        __half2 h1 = __floats2half2_rn(v.z * di, v.w * di);
        __half2* p = (__half2*)&Xh[r][c4 * 4];
        p[0] = h0; p[1] = h1;
    }
    __syncthreads();

    const int w = tid >> 5;
    wmma::fragment<wmma::accumulator, 16, 16, 16, float> c[4];
#pragma unroll
    for (int cg = 0; cg < 4; cg++) wmma::fill_fragment(c[cg], 0.f);

#pragma unroll
    for (int k = 0; k < 4; k++) {
        wmma::fragment<wmma::matrix_a, 16, 16, 16, __half, wmma::row_major> a;
        wmma::load_matrix_sync(a, &Xh[w * 16][k * 16], 72);
#pragma unroll
        for (int cg = 0; cg < 4; cg++) {
            wmma::fragment<wmma::matrix_b, 16, 16, 16, __half, wmma::row_major> b;
            wmma::load_matrix_sync(b, &Wh[k * 16][cg * 16], 72);
            wmma::mma_sync(c[cg], a, b, c[cg]);
        }
    }
    __syncthreads();

#pragma unroll
    for (int cg = 0; cg < 4; cg++)
        wmma::store_matrix_sync(&Out[w * 16][cg * 16], c[cg], 68, wmma::mem_row_major);
    __syncthreads();

#pragma unroll
    for (int i = 0; i < 4; i++) {
        int idx = tid + i * 256;
        int r   = idx >> 3;
        int q   = idx & 7;
        int row = rowBase + r;
        if (row < N_NODES) {
            const float* src = &Out[r][q * 8];
            __half2 ph[4];
            ph[0] = __floats2half2_rn(src[0], src[1]);
            ph[1] = __floats2half2_rn(src[2], src[3]);
            ph[2] = __floats2half2_rn(src[4], src[5]);
            ph[3] = __floats2half2_rn(src[6], src[7]);
            ((uint4*)hs)[(size_t)row * 8 + q] = *(uint4*)ph;
        }
    }
}

// ---------------- fp16 accumulate helper: a[0..7] += unpack(v) ----------------
__device__ __forceinline__ void acc_u4(float* a, uint4 v) {
    float2 f0 = __half22float2(*(__half2*)&v.x);
    float2 f1 = __half22float2(*(__half2*)&v.y);
    float2 f2 = __half22float2(*(__half2*)&v.z);
    float2 f3 = __half22float2(*(__half2*)&v.w);
    a[0] += f0.x; a[1] += f0.y; a[2] += f1.x; a[3] += f1.y;
    a[4] += f2.x; a[5] += f2.y; a[6] += f3.x; a[7] += f3.y;
}

// ---------------- warp-per-node gather core ----------------
// One warp handles one node: lane = (esub 0..3) x (lane8 0..7).
// esub strides over edges, lane8 over 8-half feature chunks.
// After the loop, shuffle-reduce esub partials; esub==0 lanes hold the result.
__device__ __forceinline__ void gather_node(const uint4* hs4, int node,
                                            int lane8, int esub, float* a) {
    int start = g_off[node];
    int cnt   = g_deg[node] - 1;

    float b[8] = {0.f, 0.f, 0.f, 0.f, 0.f, 0.f, 0.f, 0.f};

    if (esub == 0) acc_u4(a, hs4[(size_t)node * 8 + lane8]);   // self term

    int i = esub;
    for (; i + 4 < cnt; i += 8) {                 // 2-way ILP banks
        int s0 = g_csr[start + i];
        int s1 = g_csr[start + i + 4];
        uint4 v0 = hs4[(size_t)s0 * 8 + lane8];
        uint4 v1 = hs4[(size_t)s1 * 8 + lane8];
        acc_u4(a, v0);
        acc_u4(b, v1);
    }
    if (i < cnt) {
        int s0 = g_csr[start + i];
        acc_u4(a, hs4[(size_t)s0 * 8 + lane8]);
    }
#pragma unroll
    for (int j = 0; j < 8; j++) a[j] += b[j];

    // reduce across the 4 esub groups (stride 16 then 8)
#pragma unroll
    for (int j = 0; j < 8; j++) {
        a[j] += __shfl_down_sync(0xffffffffu, a[j], 16);
        a[j] += __shfl_down_sync(0xffffffffu, a[j], 8);
    }
}

// ---------------- layer-1 gather: agg[n] = dinv[n]*(self+sum) + b1 ----------------
__global__ __launch_bounds__(256) void k_gather1(const __half* __restrict__ hs,
                                                 const float* __restrict__ bias,
                                                 float* __restrict__ agg) {
    int warp = (blockIdx.x * 256 + threadIdx.x) >> 5;
    if (warp >= N_NODES) return;
    int lane8 = threadIdx.x & 7;
    int esub  = (threadIdx.x >> 3) & 3;

    float a[8] = {0.f, 0.f, 0.f, 0.f, 0.f, 0.f, 0.f, 0.f};
    gather_node((const uint4*)hs, warp, lane8, esub, a);

    if (esub == 0) {
        float dv = g_dinv[warp];
        float4 bv0 = ((const float4*)bias)[lane8 * 2 + 0];
        float4 bv1 = ((const float4*)bias)[lane8 * 2 + 1];
        float4 o0 = make_float4(dv * a[0] + bv0.x, dv * a[1] + bv0.y,
                                dv * a[2] + bv0.z, dv * a[3] + bv0.w);
        float4 o1 = make_float4(dv * a[4] + bv1.x, dv * a[5] + bv1.y,
                                dv * a[6] + bv1.z, dv * a[7] + bv1.w);
        float4* op = (float4*)(agg + (size_t)warp * 64 + lane8 * 8);
        op[0] = o0;
        op[1] = o1;
    }
}

// ---------------- layer-2 gather fused with pool: RED node result into g_pool[batch[n]] ----------------
// bias b2 is deferred to the head (commutes past the mean; no relu on layer 2).
__global__ __launch_bounds__(256) void k_gather2_pool(const __half* __restrict__ hs,
                                                      const int* __restrict__ batch) {
    int warp = (blockIdx.x * 256 + threadIdx.x) >> 5;
    if (warp >= N_NODES) return;
    int lane8 = threadIdx.x & 7;
    int esub  = (threadIdx.x >> 3) & 3;

    float a[8] = {0.f, 0.f, 0.f, 0.f, 0.f, 0.f, 0.f, 0.f};
    gather_node((const uint4*)hs, warp, lane8, esub, a);

    if (esub == 0) {
        float dv = g_dinv[warp];
        int g = batch[warp];
        float* p = g_pool + (size_t)g * 64 + lane8 * 8;
        asm volatile("red.global.add.v4.f32 [%0], {%1, %2, %3, %4};"
                     :: "l"(p), "f"(dv * a[0]), "f"(dv * a[1]),
                        "f"(dv * a[2]), "f"(dv * a[3]) : "memory");
        asm volatile("red.global.add.v4.f32 [%0], {%1, %2, %3, %4};"
                     :: "l"(p + 4), "f"(dv * a[4]), "f"(dv * a[5]),
                        "f"(dv * a[6]), "f"(dv * a[7]) : "memory");
    }
}

// ---------------- head: mean (+b2) + MLP ----------------
__global__ __launch_bounds__(64) void k_head(const int* __restrict__ batch,
                                             const float* __restrict__ b2,
                                             const float* __restrict__ lw1,
                                             const float* __restrict__ lb1,
                                             const float* __restrict__ lw2,
                                             const float* __restrict__ lb2,
                                             float* __restrict__ out) {
    int g = blockIdx.x;
    int tid = threadIdx.x;  // 64

    // binary-search graph boundaries in the sorted batch array -> count
    int l = 0, r = N_NODES;
    while (l < r) { int m = (l + r) >> 1; if (batch[m] < g) l = m + 1; else r = m; }
    int lo = l;
    r = N_NODES;
    while (l < r) { int m = (l + r) >> 1; if (batch[m] < g + 1) l = m + 1; else r = m; }
    int cnt = l - lo;

    // pooled mean; empty graph -> 0 (matches reference: segment_sum gives 0 rows)
    float pooled = 0.f;
    if (cnt > 0) pooled = g_pool[(size_t)g * 64 + tid] / (float)cnt + b2[tid];

    __shared__ float sp[64];
    __shared__ float sz[32];
    sp[tid] = pooled;
    __syncthreads();

    if (tid < 32) {
        float z = lb1[tid];
#pragma unroll 8
        for (int k = 0; k < 64; k++) z += sp[k] * lw1[k * 32 + tid];
        sz[tid] = fmaxf(z, 0.f);
    }
    __syncthreads();

    if (tid < 8) {
        float o = lb2[tid];
#pragma unroll
        for (int j = 0; j < 32; j++) o += sz[j] * lw2[j * 8 + tid];
        out[g * 8 + tid] = o;
    }
}

// ---------------- launch ----------------
extern "C" void kernel_launch(void* const* d_in, const int* in_sizes, int n_in,
                              void* d_out, int out_size) {
    const float* x   = (const float*)d_in[0];
    const int*   ei  = (const int*)d_in[1];
    const int*   bat = (const int*)d_in[2];
    const float* W1  = (const float*)d_in[3];
    const float* b1  = (const float*)d_in[4];
    const float* W2  = (const float*)d_in[5];
    const float* b2  = (const float*)d_in[6];
    const float* lw1 = (const float*)d_in[7];
    const float* lb1 = (const float*)d_in[8];
    const float* lw2 = (const float*)d_in[9];
    const float* lb2 = (const float*)d_in[10];
    float* out = (float*)d_out;

    __half* hs;
    float* agg;
    cudaGetSymbolAddress((void**)&hs,  g_hs);
    cudaGetSymbolAddress((void**)&agg, g_agg);

    static cudaStream_t s2 = nullptr;
    static cudaEvent_t evFork = nullptr, evJoin = nullptr;
    if (s2 == nullptr) {
        cudaStreamCreateWithFlags(&s2, cudaStreamNonBlocking);
        cudaEventCreateWithFlags(&evFork, cudaEventDisableTiming);
        cudaEventCreateWithFlags(&evJoin, cudaEventDisableTiming);
    }

    const int nblk = (N_NODES + 255) / 256;
    const int eblk = (N_EDGES + 255) / 256;
    const int gemm_blocks = (N_NODES + 127) / 128;
    const int gath_blocks = (N_NODES * 32) / 256;   // one warp per node

    // serial prefix: degrees + dinv (GEMM input scaling needs dinv)
    k_deg_init<<<nblk, 256>>>();
    k_deg_count<<<(N_EDGES / 4 + 255) / 256, 256>>>(ei);
    k_dinv<<<nblk, 256>>>();

    // fork: scan+fill on s2 || GEMM1 on main
    cudaEventRecord(evFork, 0);
    cudaStreamWaitEvent(s2, evFork, 0);

    k_scanA<<<NB_SCAN, 256, 0, s2>>>();
    k_scanB<<<1, 512, 0, s2>>>();
    k_scanC<<<nblk, 256, 0, s2>>>();
    k_fill<<<eblk, 256, 0, s2>>>(ei);

    k_gcn_gemm<false><<<gemm_blocks, 256>>>(x, W1, hs);   // concurrent

    cudaEventRecord(evJoin, s2);
    cudaStreamWaitEvent(0, evJoin, 0);

    // layer 1 aggregation (+ b1, written to agg)
    k_gather1<<<gath_blocks, 256>>>(hs, b1, agg);

    // layer 2: GEMM then gather fused with pool RED (b2 deferred to head)
    k_gcn_gemm<true><<<gemm_blocks, 256>>>(agg, W2, hs);
    k_gather2_pool<<<gath_blocks, 256>>>(hs, bat);

    // head: mean + b2 + MLP
    k_head<<<N_GRAPHS, 64>>>(bat, b2, lw1, lb1, lw2, lb2, out);
}

// round 9
// speedup vs baseline: 1.1311x; 1.1311x over previous
#include <cuda_runtime.h>
#include <cuda_fp16.h>
#include <mma.h>

using namespace nvcuda;

#define N_NODES  100000
#define N_EDGES  1600000
#define N_GRAPHS 1000
#define D        64
#define NB_SCAN  ((N_NODES + 255) / 256)   // 391

// ---------------- device scratch (no allocations allowed) ----------------
__device__ int    g_deg[N_NODES];
__device__ int    g_off[N_NODES];           // CSR row offsets
__device__ int    g_cursor[N_NODES];        // fill cursors
__device__ int    g_bsum[NB_SCAN];
__device__ int    g_boff[NB_SCAN];
__device__ int    g_csr[N_EDGES];           // src indices grouped by dst
__device__ float  g_dinv[N_NODES];
__device__ __half g_hs[(size_t)N_NODES * D];    // fp16 prescaled messages
__device__ float  g_agg[(size_t)N_NODES * D];   // layer-1 aggregation output
__device__ float  g_pool[(size_t)N_GRAPHS * D]; // per-graph feature sums (RED target)

// ---------------- degree / norm (also zeroes pool sums) ----------------
__global__ void k_deg_init() {
    int i = blockIdx.x * blockDim.x + threadIdx.x;
    if (i < N_NODES) g_deg[i] = 1;  // self-loop
    if (i < N_GRAPHS * D) g_pool[i] = 0.f;
}

__global__ void k_deg_count(const int* __restrict__ ei) {
    int t = blockIdx.x * blockDim.x + threadIdx.x;
    if (t < N_EDGES / 4) {
        int4 d = ((const int4*)(ei + N_EDGES))[t];
        atomicAdd(&g_deg[d.x], 1);
        atomicAdd(&g_deg[d.y], 1);
        atomicAdd(&g_deg[d.z], 1);
        atomicAdd(&g_deg[d.w], 1);
    }
}

__global__ void k_dinv() {
    int i = blockIdx.x * blockDim.x + threadIdx.x;
    if (i < N_NODES) {
        g_dinv[i] = rsqrtf((float)g_deg[i]);
        g_cursor[i] = 0;
    }
}

// ---------------- 3-pass exclusive scan of (deg-1) into g_off ----------------
__global__ __launch_bounds__(256) void k_scanA() {
    __shared__ int s[256];
    int tid = threadIdx.x;
    int i = blockIdx.x * 256 + tid;
    int v = (i < N_NODES) ? (g_deg[i] - 1) : 0;
    s[tid] = v;
    __syncthreads();
#pragma unroll
    for (int o = 1; o < 256; o <<= 1) {
        int t = (tid >= o) ? s[tid - o] : 0;
        __syncthreads();
        s[tid] += t;
        __syncthreads();
    }
    if (i < N_NODES) g_off[i] = s[tid] - v;          // exclusive
    if (tid == 255) g_bsum[blockIdx.x] = s[255];
}

__global__ __launch_bounds__(512) void k_scanB() {
    __shared__ int s[512];
    int tid = threadIdx.x;
    int v = (tid < NB_SCAN) ? g_bsum[tid] : 0;
    s[tid] = v;
    __syncthreads();
#pragma unroll
    for (int o = 1; o < 512; o <<= 1) {
        int t = (tid >= o) ? s[tid - o] : 0;
        __syncthreads();
        s[tid] += t;
        __syncthreads();
    }
    if (tid < NB_SCAN) g_boff[tid] = s[tid] - v;     // exclusive
}

__global__ __launch_bounds__(256) void k_scanC() {
    int i = blockIdx.x * 256 + threadIdx.x;
    if (i < N_NODES) g_off[i] += g_boff[i >> 8];
}

// ---------------- CSR fill: group src indices by dst ----------------
__global__ __launch_bounds__(256) void k_fill(const int* __restrict__ ei) {
    int e = blockIdx.x * blockDim.x + threadIdx.x;
    if (e < N_EDGES) {
        int src = ei[e];
        int dst = ei[N_EDGES + e];
        int pos = g_off[dst] + atomicAdd(&g_cursor[dst], 1);
        g_csr[pos] = src;
    }
}

// ---------------- tensor-core GEMM: hs = fp16( (act(in)*dinv[row]) @ W ) ----------------
template<bool RELU_IN>
__global__ __launch_bounds__(256) void k_gcn_gemm(const float* __restrict__ in,
                                                  const float* __restrict__ W,
                                                  __half* __restrict__ hs) {
    __shared__ __align__(16) char smem_raw[128 * 68 * 4];
    __half (*Xh)[72] = (__half(*)[72])smem_raw;              // 128x72 fp16
    __half (*Wh)[72] = (__half(*)[72])(smem_raw + 18432);    // 64x72  fp16
    float  (*Out)[68] = (float(*)[68])smem_raw;              // 128x68 fp32 (after sync)

    const int tid = threadIdx.x;
    const int rowBase = blockIdx.x * 128;

#pragma unroll
    for (int i = 0; i < 4; i++) {
        int f4 = tid + i * 256;
        int r  = f4 >> 4;
        int c4 = f4 & 15;
        float4 v = ((const float4*)W)[f4];
        __half2 h0 = __floats2half2_rn(v.x, v.y);
        __half2 h1 = __floats2half2_rn(v.z, v.w);
        __half2* p = (__half2*)&Wh[r][c4 * 4];
        p[0] = h0; p[1] = h1;
    }

#pragma unroll
    for (int i = 0; i < 8; i++) {
        int f4  = tid + i * 256;
        int r   = f4 >> 4;
        int c4  = f4 & 15;
        int row = rowBase + r;
        float4 v = make_float4(0.f, 0.f, 0.f, 0.f);
        float di = 0.f;
        if (row < N_NODES) {
            v = ((const float4*)in)[(size_t)row * 16 + c4];
            di = g_dinv[row];
        }
        if (RELU_IN) {
            v.x = fmaxf(v.x, 0.f); v.y = fmaxf(v.y, 0.f);
            v.z = fmaxf(v.z, 0.f); v.w = fmaxf(v.w, 0.f);
        }
        __half2 h0 = __floats2half2_rn(v.x * di, v.y * di);
        __half2 h1 = __floats2half2_rn(v.z * di, v.w * di);
        __half2* p = (__half2*)&Xh[r][c4 * 4];
        p[0] = h0; p[1] = h1;
    }
    __syncthreads();

    const int w = tid >> 5;
    wmma::fragment<wmma::accumulator, 16, 16, 16, float> c[4];
#pragma unroll
    for (int cg = 0; cg < 4; cg++) wmma::fill_fragment(c[cg], 0.f);

#pragma unroll
    for (int k = 0; k < 4; k++) {
        wmma::fragment<wmma::matrix_a, 16, 16, 16, __half, wmma::row_major> a;
        wmma::load_matrix_sync(a, &Xh[w * 16][k * 16], 72);
#pragma unroll
        for (int cg = 0; cg < 4; cg++) {
            wmma::fragment<wmma::matrix_b, 16, 16, 16, __half, wmma::row_major> b;
            wmma::load_matrix_sync(b, &Wh[k * 16][cg * 16], 72);
            wmma::mma_sync(c[cg], a, b, c[cg]);
        }
    }
    __syncthreads();

#pragma unroll
    for (int cg = 0; cg < 4; cg++)
        wmma::store_matrix_sync(&Out[w * 16][cg * 16], c[cg], 68, wmma::mem_row_major);
    __syncthreads();

#pragma unroll
    for (int i = 0; i < 4; i++) {
        int idx = tid + i * 256;
        int r   = idx >> 3;
        int q   = idx & 7;
        int row = rowBase + r;
        if (row < N_NODES) {
            const float* src = &Out[r][q * 8];
            __half2 ph[4];
            ph[0] = __floats2half2_rn(src[0], src[1]);
            ph[1] = __floats2half2_rn(src[2], src[3]);
            ph[2] = __floats2half2_rn(src[4], src[5]);
            ph[3] = __floats2half2_rn(src[6], src[7]);
            ((uint4*)hs)[(size_t)row * 8 + q] = *(uint4*)ph;
        }
    }
}

// ---------------- fp16 accumulate helper: a[0..7] += unpack(v) ----------------
__device__ __forceinline__ void acc_u4(float* a, uint4 v) {
    float2 f0 = __half22float2(*(__half2*)&v.x);
    float2 f1 = __half22float2(*(__half2*)&v.y);
    float2 f2 = __half22float2(*(__half2*)&v.z);
    float2 f3 = __half22float2(*(__half2*)&v.w);
    a[0] += f0.x; a[1] += f0.y; a[2] += f1.x; a[3] += f1.y;
    a[4] += f2.x; a[5] += f2.y; a[6] += f3.x; a[7] += f3.y;
}

// ---------------- sequential per-node gather core (R7 layout: 8 lanes/node) ----------------
// Accumulates self + all neighbors into a[8]; each lane owns 8 feature halves.
__device__ __forceinline__ void gather_seq(const uint4* hs4, int node, int lane,
                                           float* a) {
    int start = g_off[node];
    int cnt   = g_deg[node] - 1;

    float b[8] = {0.f, 0.f, 0.f, 0.f, 0.f, 0.f, 0.f, 0.f};

    acc_u4(a, hs4[(size_t)node * 8 + lane]);   // self term

    int i = 0;
    for (; i + 4 <= cnt; i += 4) {
        int s0 = g_csr[start + i + 0];
        int s1 = g_csr[start + i + 1];
        int s2 = g_csr[start + i + 2];
        int s3 = g_csr[start + i + 3];
        uint4 v0 = hs4[(size_t)s0 * 8 + lane];
        uint4 v1 = hs4[(size_t)s1 * 8 + lane];
        uint4 v2 = hs4[(size_t)s2 * 8 + lane];
        uint4 v3 = hs4[(size_t)s3 * 8 + lane];
        acc_u4(a, v0);
        acc_u4(b, v1);
        acc_u4(a, v2);
        acc_u4(b, v3);
    }
    for (; i < cnt; i++) {
        int s0 = g_csr[start + i];
        acc_u4(a, hs4[(size_t)s0 * 8 + lane]);
    }
#pragma unroll
    for (int j = 0; j < 8; j++) a[j] += b[j];
}

// ---------------- layer-1 gather: agg[n] = dinv[n]*(self+sum) + b1 ----------------
__global__ __launch_bounds__(256) void k_gather1(const __half* __restrict__ hs,
                                                 const float* __restrict__ bias,
                                                 float* __restrict__ agg) {
    int t = blockIdx.x * blockDim.x + threadIdx.x;
    int node = t >> 3;
    int lane = t & 7;
    if (node >= N_NODES) return;

    float a[8] = {0.f, 0.f, 0.f, 0.f, 0.f, 0.f, 0.f, 0.f};
    gather_seq((const uint4*)hs, node, lane, a);

    float dv = g_dinv[node];
    float4 bv0 = ((const float4*)bias)[lane * 2 + 0];
    float4 bv1 = ((const float4*)bias)[lane * 2 + 1];
    float4 o0 = make_float4(dv * a[0] + bv0.x, dv * a[1] + bv0.y,
                            dv * a[2] + bv0.z, dv * a[3] + bv0.w);
    float4 o1 = make_float4(dv * a[4] + bv1.x, dv * a[5] + bv1.y,
                            dv * a[6] + bv1.z, dv * a[7] + bv1.w);
    float4* op = (float4*)(agg + (size_t)node * 64 + lane * 8);
    op[0] = o0;
    op[1] = o1;
}

// ---------------- layer-2 gather fused with pool: RED into g_pool[batch[n]] ----------------
// bias b2 deferred to the head (commutes past the mean; no relu on layer 2).
__global__ __launch_bounds__(256) void k_gather2_pool(const __half* __restrict__ hs,
                                                      const int* __restrict__ batch) {
    int t = blockIdx.x * blockDim.x + threadIdx.x;
    int node = t >> 3;
    int lane = t & 7;
    if (node >= N_NODES) return;

    float a[8] = {0.f, 0.f, 0.f, 0.f, 0.f, 0.f, 0.f, 0.f};
    gather_seq((const uint4*)hs, node, lane, a);

    float dv = g_dinv[node];
    int g = batch[node];
    float* p = g_pool + (size_t)g * 64 + lane * 8;
    asm volatile("red.global.add.v4.f32 [%0], {%1, %2, %3, %4};"
                 :: "l"(p), "f"(dv * a[0]), "f"(dv * a[1]),
                    "f"(dv * a[2]), "f"(dv * a[3]) : "memory");
    asm volatile("red.global.add.v4.f32 [%0], {%1, %2, %3, %4};"
                 :: "l"(p + 4), "f"(dv * a[4]), "f"(dv * a[5]),
                    "f"(dv * a[6]), "f"(dv * a[7]) : "memory");
}

// ---------------- head: mean (+b2) + MLP ----------------
__global__ __launch_bounds__(64) void k_head(const int* __restrict__ batch,
                                             const float* __restrict__ b2,
                                             const float* __restrict__ lw1,
                                             const float* __restrict__ lb1,
                                             const float* __restrict__ lw2,
                                             const float* __restrict__ lb2,
                                             float* __restrict__ out) {
    int g = blockIdx.x;
    int tid = threadIdx.x;  // 64

    int l = 0, r = N_NODES;
    while (l < r) { int m = (l + r) >> 1; if (batch[m] < g) l = m + 1; else r = m; }
    int lo = l;
    r = N_NODES;
    while (l < r) { int m = (l + r) >> 1; if (batch[m] < g + 1) l = m + 1; else r = m; }
    int cnt = l - lo;

    float pooled = 0.f;
    if (cnt > 0) pooled = g_pool[(size_t)g * 64 + tid] / (float)cnt + b2[tid];

    __shared__ float sp[64];
    __shared__ float sz[32];
    sp[tid] = pooled;
    __syncthreads();

    if (tid < 32) {
        float z = lb1[tid];
#pragma unroll 8
        for (int k = 0; k < 64; k++) z += sp[k] * lw1[k * 32 + tid];
        sz[tid] = fmaxf(z, 0.f);
    }
    __syncthreads();

    if (tid < 8) {
        float o = lb2[tid];
#pragma unroll
        for (int j = 0; j < 32; j++) o += sz[j] * lw2[j * 8 + tid];
        out[g * 8 + tid] = o;
    }
}

// ---------------- launch ----------------
extern "C" void kernel_launch(void* const* d_in, const int* in_sizes, int n_in,
                              void* d_out, int out_size) {
    const float* x   = (const float*)d_in[0];
    const int*   ei  = (const int*)d_in[1];
    const int*   bat = (const int*)d_in[2];
    const float* W1  = (const float*)d_in[3];
    const float* b1  = (const float*)d_in[4];
    const float* W2  = (const float*)d_in[5];
    const float* b2  = (const float*)d_in[6];
    const float* lw1 = (const float*)d_in[7];
    const float* lb1 = (const float*)d_in[8];
    const float* lw2 = (const float*)d_in[9];
    const float* lb2 = (const float*)d_in[10];
    float* out = (float*)d_out;

    __half* hs;
    float* agg;
    cudaGetSymbolAddress((void**)&hs,  g_hs);
    cudaGetSymbolAddress((void**)&agg, g_agg);

    static cudaStream_t s2 = nullptr;
    static cudaEvent_t evFork = nullptr, evJoin = nullptr;
    if (s2 == nullptr) {
        cudaStreamCreateWithFlags(&s2, cudaStreamNonBlocking);
        cudaEventCreateWithFlags(&evFork, cudaEventDisableTiming);
        cudaEventCreateWithFlags(&evJoin, cudaEventDisableTiming);
    }

    const int nblk = (N_NODES + 255) / 256;
    const int eblk = (N_EDGES + 255) / 256;
    const int gemm_blocks = (N_NODES + 127) / 128;
    const int gath_blocks = (N_NODES * 8 + 255) / 256;

    // serial prefix: degrees + dinv (GEMM input scaling needs dinv)
    k_deg_init<<<nblk, 256>>>();
    k_deg_count<<<(N_EDGES / 4 + 255) / 256, 256>>>(ei);
    k_dinv<<<nblk, 256>>>();

    // fork: scan+fill on s2 || GEMM1 on main
    cudaEventRecord(evFork, 0);
    cudaStreamWaitEvent(s2, evFork, 0);

    k_scanA<<<NB_SCAN, 256, 0, s2>>>();
    k_scanB<<<1, 512, 0, s2>>>();
    k_scanC<<<nblk, 256, 0, s2>>>();
    k_fill<<<eblk, 256, 0, s2>>>(ei);

    k_gcn_gemm<false><<<gemm_blocks, 256>>>(x, W1, hs);   // concurrent

    cudaEventRecord(evJoin, s2);
    cudaStreamWaitEvent(0, evJoin, 0);

    // layer 1 aggregation (+ b1, written to agg)
    k_gather1<<<gath_blocks, 256>>>(hs, b1, agg);

    // layer 2: GEMM then gather fused with pool RED (b2 deferred to head)
    k_gcn_gemm<true><<<gemm_blocks, 256>>>(agg, W2, hs);
    k_gather2_pool<<<gath_blocks, 256>>>(hs, bat);

    // head: mean + b2 + MLP
    k_head<<<N_GRAPHS, 64>>>(bat, b2, lw1, lb1, lw2, lb2, out);
}

// round 10
// speedup vs baseline: 1.2368x; 1.0934x over previous
#include <cuda_runtime.h>
#include <cuda_fp16.h>
#include <mma.h>

using namespace nvcuda;

#define N_NODES  100000
#define N_EDGES  1600000
#define N_GRAPHS 1000
#define D        64
#define NB_SCAN  ((N_NODES + 255) / 256)   // 391

// ---------------- device scratch (no allocations allowed) ----------------
__device__ int    g_deg[N_NODES];           // in-degree (0-based; self-loop added at use)
__device__ int    g_off[N_NODES];           // CSR row offsets (per-block exclusive scan)
__device__ int    g_cursor[N_NODES];        // fill cursors
__device__ int    g_bsum[NB_SCAN];
__device__ int    g_boff[NB_SCAN];          // block offsets (added at use sites)
__device__ int    g_csr[N_EDGES];           // src indices grouped by dst
__device__ float  g_dinv[N_NODES];          // rsqrt(deg+1)
__device__ __half g_hs[(size_t)N_NODES * D];  // fp16 prescaled GEMM outputs
__device__ __half g_ha[(size_t)N_NODES * D];  // fp16 aggregation outputs

// ---------------- degree count (deg starts at 0 via memset) ----------------
__global__ void k_deg_count(const int* __restrict__ ei) {
    int t = blockIdx.x * blockDim.x + threadIdx.x;
    if (t < N_EDGES / 4) {
        int4 d = ((const int4*)(ei + N_EDGES))[t];
        atomicAdd(&g_deg[d.x], 1);
        atomicAdd(&g_deg[d.y], 1);
        atomicAdd(&g_deg[d.z], 1);
        atomicAdd(&g_deg[d.w], 1);
    }
}

__global__ void k_dinv() {
    int i = blockIdx.x * blockDim.x + threadIdx.x;
    if (i < N_NODES) g_dinv[i] = rsqrtf((float)(g_deg[i] + 1));
}

// ---------------- 2-pass exclusive scan of deg into off/boff ----------------
__global__ __launch_bounds__(256) void k_scanA() {
    __shared__ int s[256];
    int tid = threadIdx.x;
    int i = blockIdx.x * 256 + tid;
    int v = (i < N_NODES) ? g_deg[i] : 0;
    s[tid] = v;
    __syncthreads();
#pragma unroll
    for (int o = 1; o < 256; o <<= 1) {
        int t = (tid >= o) ? s[tid - o] : 0;
        __syncthreads();
        s[tid] += t;
        __syncthreads();
    }
    if (i < N_NODES) g_off[i] = s[tid] - v;          // exclusive (within block)
    if (tid == 255) g_bsum[blockIdx.x] = s[255];
}

__global__ __launch_bounds__(512) void k_scanB() {
    __shared__ int s[512];
    int tid = threadIdx.x;
    int v = (tid < NB_SCAN) ? g_bsum[tid] : 0;
    s[tid] = v;
    __syncthreads();
#pragma unroll
    for (int o = 1; o < 512; o <<= 1) {
        int t = (tid >= o) ? s[tid - o] : 0;
        __syncthreads();
        s[tid] += t;
        __syncthreads();
    }
    if (tid < NB_SCAN) g_boff[tid] = s[tid] - v;     // exclusive
}

// ---------------- CSR fill: off + boff folded in ----------------
__global__ __launch_bounds__(256) void k_fill(const int* __restrict__ ei) {
    int e = blockIdx.x * blockDim.x + threadIdx.x;
    if (e < N_EDGES) {
        int src = ei[e];
        int dst = ei[N_EDGES + e];
        int pos = g_off[dst] + g_boff[dst >> 8] + atomicAdd(&g_cursor[dst], 1);
        g_csr[pos] = src;
    }
}

// ---------------- GEMM layer 1: hs = fp16( (x*dinv[row]) @ W1 ), x fp32 ----------------
__global__ __launch_bounds__(256) void k_gemm_l1(const float* __restrict__ in,
                                                 const float* __restrict__ W,
                                                 __half* __restrict__ hs) {
    __shared__ __align__(16) char smem_raw[128 * 68 * 4];
    __half (*Xh)[72] = (__half(*)[72])smem_raw;
    __half (*Wh)[72] = (__half(*)[72])(smem_raw + 18432);
    float  (*Out)[68] = (float(*)[68])smem_raw;

    const int tid = threadIdx.x;
    const int rowBase = blockIdx.x * 128;

#pragma unroll
    for (int i = 0; i < 4; i++) {
        int f4 = tid + i * 256;
        int r  = f4 >> 4;
        int c4 = f4 & 15;
        float4 v = ((const float4*)W)[f4];
        __half2* p = (__half2*)&Wh[r][c4 * 4];
        p[0] = __floats2half2_rn(v.x, v.y);
        p[1] = __floats2half2_rn(v.z, v.w);
    }

#pragma unroll
    for (int i = 0; i < 8; i++) {
        int f4  = tid + i * 256;
        int r   = f4 >> 4;
        int c4  = f4 & 15;
        int row = rowBase + r;
        float4 v = make_float4(0.f, 0.f, 0.f, 0.f);
        float di = 0.f;
        if (row < N_NODES) {
            v = ((const float4*)in)[(size_t)row * 16 + c4];
            di = g_dinv[row];
        }
        __half2* p = (__half2*)&Xh[r][c4 * 4];
        p[0] = __floats2half2_rn(v.x * di, v.y * di);
        p[1] = __floats2half2_rn(v.z * di, v.w * di);
    }
    __syncthreads();

    const int w = tid >> 5;
    wmma::fragment<wmma::accumulator, 16, 16, 16, float> c[4];
#pragma unroll
    for (int cg = 0; cg < 4; cg++) wmma::fill_fragment(c[cg], 0.f);
#pragma unroll
    for (int k = 0; k < 4; k++) {
        wmma::fragment<wmma::matrix_a, 16, 16, 16, __half, wmma::row_major> a;
        wmma::load_matrix_sync(a, &Xh[w * 16][k * 16], 72);
#pragma unroll
        for (int cg = 0; cg < 4; cg++) {
            wmma::fragment<wmma::matrix_b, 16, 16, 16, __half, wmma::row_major> b;
            wmma::load_matrix_sync(b, &Wh[k * 16][cg * 16], 72);
            wmma::mma_sync(c[cg], a, b, c[cg]);
        }
    }
    __syncthreads();
#pragma unroll
    for (int cg = 0; cg < 4; cg++)
        wmma::store_matrix_sync(&Out[w * 16][cg * 16], c[cg], 68, wmma::mem_row_major);
    __syncthreads();

#pragma unroll
    for (int i = 0; i < 4; i++) {
        int idx = tid + i * 256;
        int r   = idx >> 3;
        int q   = idx & 7;
        int row = rowBase + r;
        if (row < N_NODES) {
            const float* src = &Out[r][q * 8];
            __half2 ph[4];
            ph[0] = __floats2half2_rn(src[0], src[1]);
            ph[1] = __floats2half2_rn(src[2], src[3]);
            ph[2] = __floats2half2_rn(src[4], src[5]);
            ph[3] = __floats2half2_rn(src[6], src[7]);
            ((uint4*)hs)[(size_t)row * 8 + q] = *(uint4*)ph;
        }
    }
}

// ---------------- GEMM layer 2: hs = fp16( (ha*dinv[row]) @ W2 ), ha fp16 ----------------
__global__ __launch_bounds__(256) void k_gemm_l2(const __half* __restrict__ in,
                                                 const float* __restrict__ W,
                                                 __half* __restrict__ hs) {
    __shared__ __align__(16) char smem_raw[128 * 68 * 4];
    __half (*Xh)[72] = (__half(*)[72])smem_raw;
    __half (*Wh)[72] = (__half(*)[72])(smem_raw + 18432);
    float  (*Out)[68] = (float(*)[68])smem_raw;

    const int tid = threadIdx.x;
    const int rowBase = blockIdx.x * 128;

#pragma unroll
    for (int i = 0; i < 4; i++) {
        int f4 = tid + i * 256;
        int r  = f4 >> 4;
        int c4 = f4 & 15;
        float4 v = ((const float4*)W)[f4];
        __half2* p = (__half2*)&Wh[r][c4 * 4];
        p[0] = __floats2half2_rn(v.x, v.y);
        p[1] = __floats2half2_rn(v.z, v.w);
    }

    // stage fp16 input: 128 rows x 8 uint4 (8 halves each) = 1024, 4 per thread
#pragma unroll
    for (int i = 0; i < 4; i++) {
        int idx = tid + i * 256;        // 0..1023
        int r   = idx >> 3;             // 0..127
        int q   = idx & 7;              // 8-half chunk
        int row = rowBase + r;
        uint4 v = make_uint4(0u, 0u, 0u, 0u);
        float di = 0.f;
        if (row < N_NODES) {
            v = ((const uint4*)in)[(size_t)row * 8 + q];
            di = g_dinv[row];
        }
        __half2 ph[4];
        float2 f0 = __half22float2(*(__half2*)&v.x);
        float2 f1 = __half22float2(*(__half2*)&v.y);
        float2 f2 = __half22float2(*(__half2*)&v.z);
        float2 f3 = __half22float2(*(__half2*)&v.w);
        ph[0] = __floats2half2_rn(f0.x * di, f0.y * di);
        ph[1] = __floats2half2_rn(f1.x * di, f1.y * di);
        ph[2] = __floats2half2_rn(f2.x * di, f2.y * di);
        ph[3] = __floats2half2_rn(f3.x * di, f3.y * di);
        *(uint4*)&Xh[r][q * 8] = *(uint4*)ph;
    }
    __syncthreads();

    const int w = tid >> 5;
    wmma::fragment<wmma::accumulator, 16, 16, 16, float> c[4];
#pragma unroll
    for (int cg = 0; cg < 4; cg++) wmma::fill_fragment(c[cg], 0.f);
#pragma unroll
    for (int k = 0; k < 4; k++) {
        wmma::fragment<wmma::matrix_a, 16, 16, 16, __half, wmma::row_major> a;
        wmma::load_matrix_sync(a, &Xh[w * 16][k * 16], 72);
#pragma unroll
        for (int cg = 0; cg < 4; cg++) {
            wmma::fragment<wmma::matrix_b, 16, 16, 16, __half, wmma::row_major> b;
            wmma::load_matrix_sync(b, &Wh[k * 16][cg * 16], 72);
            wmma::mma_sync(c[cg], a, b, c[cg]);
        }
    }
    __syncthreads();
#pragma unroll
    for (int cg = 0; cg < 4; cg++)
        wmma::store_matrix_sync(&Out[w * 16][cg * 16], c[cg], 68, wmma::mem_row_major);
    __syncthreads();

#pragma unroll
    for (int i = 0; i < 4; i++) {
        int idx = tid + i * 256;
        int r   = idx >> 3;
        int q   = idx & 7;
        int row = rowBase + r;
        if (row < N_NODES) {
            const float* src = &Out[r][q * 8];
            __half2 ph[4];
            ph[0] = __floats2half2_rn(src[0], src[1]);
            ph[1] = __floats2half2_rn(src[2], src[3]);
            ph[2] = __floats2half2_rn(src[4], src[5]);
            ph[3] = __floats2half2_rn(src[6], src[7]);
            ((uint4*)hs)[(size_t)row * 8 + q] = *(uint4*)ph;
        }
    }
}

// ---------------- fp16 accumulate helper: a[0..7] += unpack(v) ----------------
__device__ __forceinline__ void acc_u4(float* a, uint4 v) {
    float2 f0 = __half22float2(*(__half2*)&v.x);
    float2 f1 = __half22float2(*(__half2*)&v.y);
    float2 f2 = __half22float2(*(__half2*)&v.z);
    float2 f3 = __half22float2(*(__half2*)&v.w);
    a[0] += f0.x; a[1] += f0.y; a[2] += f1.x; a[3] += f1.y;
    a[4] += f2.x; a[5] += f2.y; a[6] += f3.x; a[7] += f3.y;
}

// ---------------- CSR gather: ha[n] = act( dinv[n]*(hs[n]+sum hs[s]) + bias ) fp16 ----------------
// 8 lanes per node, sequential edge loop with dual accumulator banks (R7 layout).
template<bool RELU_OUT>
__global__ __launch_bounds__(256) void k_gather(const __half* __restrict__ hs,
                                                const float* __restrict__ bias,
                                                __half* __restrict__ ha) {
    int t = blockIdx.x * blockDim.x + threadIdx.x;
    int node = t >> 3;
    int lane = t & 7;
    if (node >= N_NODES) return;

    const uint4* hs4 = (const uint4*)hs;
    int start = g_off[node] + g_boff[node >> 8];
    int cnt   = g_deg[node];

    float a[8] = {0.f, 0.f, 0.f, 0.f, 0.f, 0.f, 0.f, 0.f};
    float b[8] = {0.f, 0.f, 0.f, 0.f, 0.f, 0.f, 0.f, 0.f};

    acc_u4(a, hs4[(size_t)node * 8 + lane]);   // self term

    int i = 0;
    for (; i + 4 <= cnt; i += 4) {
        int s0 = g_csr[start + i + 0];
        int s1 = g_csr[start + i + 1];
        int s2 = g_csr[start + i + 2];
        int s3 = g_csr[start + i + 3];
        uint4 v0 = hs4[(size_t)s0 * 8 + lane];
        uint4 v1 = hs4[(size_t)s1 * 8 + lane];
        uint4 v2 = hs4[(size_t)s2 * 8 + lane];
        uint4 v3 = hs4[(size_t)s3 * 8 + lane];
        acc_u4(a, v0);
        acc_u4(b, v1);
        acc_u4(a, v2);
        acc_u4(b, v3);
    }
    for (; i < cnt; i++) {
        int s0 = g_csr[start + i];
        acc_u4(a, hs4[(size_t)s0 * 8 + lane]);
    }

    float dv = g_dinv[node];
    float4 bv0 = ((const float4*)bias)[lane * 2 + 0];
    float4 bv1 = ((const float4*)bias)[lane * 2 + 1];
    float o[8];
    o[0] = dv * (a[0] + b[0]) + bv0.x;
    o[1] = dv * (a[1] + b[1]) + bv0.y;
    o[2] = dv * (a[2] + b[2]) + bv0.z;
    o[3] = dv * (a[3] + b[3]) + bv0.w;
    o[4] = dv * (a[4] + b[4]) + bv1.x;
    o[5] = dv * (a[5] + b[5]) + bv1.y;
    o[6] = dv * (a[6] + b[6]) + bv1.z;
    o[7] = dv * (a[7] + b[7]) + bv1.w;
    if (RELU_OUT) {
#pragma unroll
        for (int j = 0; j < 8; j++) o[j] = fmaxf(o[j], 0.f);
    }
    __half2 ph[4];
    ph[0] = __floats2half2_rn(o[0], o[1]);
    ph[1] = __floats2half2_rn(o[2], o[3]);
    ph[2] = __floats2half2_rn(o[4], o[5]);
    ph[3] = __floats2half2_rn(o[6], o[7]);
    ((uint4*)ha)[(size_t)node * 8 + lane] = *(uint4*)ph;
}

// ---------------- fused mean-pool (batch is sorted) + MLP head ----------------
__global__ __launch_bounds__(64) void k_pool_head(const __half* __restrict__ ha,
                                                  const int* __restrict__ batch,
                                                  const float* __restrict__ lw1,
                                                  const float* __restrict__ lb1,
                                                  const float* __restrict__ lw2,
                                                  const float* __restrict__ lb2,
                                                  float* __restrict__ out) {
    int g = blockIdx.x;
    int tid = threadIdx.x;  // 64

    int l = 0, r = N_NODES;
    while (l < r) { int m = (l + r) >> 1; if (batch[m] < g) l = m + 1; else r = m; }
    int lo = l;
    r = N_NODES;
    while (l < r) { int m = (l + r) >> 1; if (batch[m] < g + 1) l = m + 1; else r = m; }
    int hi = l;

    float acc = 0.f;
    for (int n = lo; n < hi; n++) acc += __half2float(ha[(size_t)n * 64 + tid]);
    int cnt = hi - lo;
    float pooled = acc / (float)(cnt > 0 ? cnt : 1);

    __shared__ float sp[64];
    __shared__ float sz[32];
    sp[tid] = pooled;
    __syncthreads();

    if (tid < 32) {
        float z = lb1[tid];
#pragma unroll 8
        for (int k = 0; k < 64; k++) z += sp[k] * lw1[k * 32 + tid];
        sz[tid] = fmaxf(z, 0.f);
    }
    __syncthreads();

    if (tid < 8) {
        float o = lb2[tid];
#pragma unroll
        for (int j = 0; j < 32; j++) o += sz[j] * lw2[j * 8 + tid];
        out[g * 8 + tid] = o;
    }
}

// ---------------- launch ----------------
extern "C" void kernel_launch(void* const* d_in, const int* in_sizes, int n_in,
                              void* d_out, int out_size) {
    const float* x   = (const float*)d_in[0];
    const int*   ei  = (const int*)d_in[1];
    const int*   bat = (const int*)d_in[2];
    const float* W1  = (const float*)d_in[3];
    const float* b1  = (const float*)d_in[4];
    const float* W2  = (const float*)d_in[5];
    const float* b2  = (const float*)d_in[6];
    const float* lw1 = (const float*)d_in[7];
    const float* lb1 = (const float*)d_in[8];
    const float* lw2 = (const float*)d_in[9];
    const float* lb2 = (const float*)d_in[10];
    float* out = (float*)d_out;

    __half *hs, *ha;
    int *degp, *curp;
    cudaGetSymbolAddress((void**)&hs,   g_hs);
    cudaGetSymbolAddress((void**)&ha,   g_ha);
    cudaGetSymbolAddress((void**)&degp, g_deg);
    cudaGetSymbolAddress((void**)&curp, g_cursor);

    static cudaStream_t s2 = nullptr;
    static cudaEvent_t evFork = nullptr, evJoin = nullptr;
    if (s2 == nullptr) {
        cudaStreamCreateWithFlags(&s2, cudaStreamNonBlocking);
        cudaEventCreateWithFlags(&evFork, cudaEventDisableTiming);
        cudaEventCreateWithFlags(&evJoin, cudaEventDisableTiming);
    }

    const int nblk = (N_NODES + 255) / 256;
    const int eblk = (N_EDGES + 255) / 256;
    const int gemm_blocks = (N_NODES + 127) / 128;
    const int gath_blocks = (N_NODES * 8 + 255) / 256;

    // zero deg + cursors (memset nodes), count degrees, dinv = rsqrt(deg+1)
    cudaMemsetAsync(degp, 0, N_NODES * sizeof(int), 0);
    cudaMemsetAsync(curp, 0, N_NODES * sizeof(int), 0);
    k_deg_count<<<(N_EDGES / 4 + 255) / 256, 256>>>(ei);
    k_dinv<<<nblk, 256>>>();

    // fork: scan+fill on s2 || GEMM1 on main
    cudaEventRecord(evFork, 0);
    cudaStreamWaitEvent(s2, evFork, 0);

    k_scanA<<<NB_SCAN, 256, 0, s2>>>();
    k_scanB<<<1, 512, 0, s2>>>();
    k_fill<<<eblk, 256, 0, s2>>>(ei);

    k_gemm_l1<<<gemm_blocks, 256>>>(x, W1, hs);   // concurrent

    cudaEventRecord(evJoin, s2);
    cudaStreamWaitEvent(0, evJoin, 0);

    // layer 1 aggregation: ha = relu(dinv*(sum)+b1) in fp16
    k_gather<true><<<gath_blocks, 256>>>(hs, b1, ha);

    // layer 2: fp16-input GEMM, then gather (no relu) back into ha
    k_gemm_l2<<<gemm_blocks, 256>>>(ha, W2, hs);
    k_gather<false><<<gath_blocks, 256>>>(hs, b2, ha);

    // pool per graph + MLP head
    k_pool_head<<<N_GRAPHS, 64>>>(ha, bat, lw1, lb1, lw2, lb2, out);
}